// round 1
// baseline (speedup 1.0000x reference)
#include <cuda_runtime.h>

#define NPIX 65536   // 256*256

// ---------------- device scratch (static allocation, allowed) ----------------
__device__ float2 g_fA[3 * NPIX];     // FFT(A) per channel, planar [c][x][y]
__device__ float2 g_spec[15 * NPIX];  // per-kernel spectrum / half-inverted, planar [k][x][y]
__device__ float  g_Ug[15 * NPIX];    // growth(U)*P, planar [k][x][y]
__device__ float  g_Uc[3 * NPIX];     // channel-summed U, planar [c][x][y]
__device__ float  g_Asum[NPIX];       // sum_c A
__device__ float  g_mus[NPIX * 6];    // interleaved per-pixel: [c*2 + dim]

__device__ __forceinline__ float2 cmulf(float2 a, float2 b) {
    return make_float2(a.x * b.x - a.y * b.y, a.x * b.y + a.y * b.x);
}

// ---------------- 256-point Stockham radix-2 FFT in shared memory -----------
// 128 threads, data in sA on entry (after a __syncthreads by caller),
// result in sA (natural order). SIGN = -1 forward, +1 inverse (unscaled).
template <int SIGN>
__device__ __forceinline__ void fft256(float2* sA, float2* sB, int t) {
    float2* x = sA;
    float2* y = sB;
#pragma unroll
    for (int i = 0; i < 8; i++) {
        int s = 1 << i;
        int n = 256 >> i;
        int m = n >> 1;
        int p = t >> i;
        int q = t & (s - 1);
        float2 a = x[q + s * p];
        float2 b = x[q + s * (p + m)];
        float ang = (float)SIGN * 6.283185307179586f * (float)p / (float)n;
        float sn, cs;
        __sincosf(ang, &sn, &cs);
        y[q + s * (2 * p)] = make_float2(a.x + b.x, a.y + b.y);
        float2 d = make_float2(a.x - b.x, a.y - b.y);
        y[q + s * (2 * p + 1)] = cmulf(d, make_float2(cs, sn));
        __syncthreads();
        float2* tmp = x; x = y; y = tmp;
    }
    // 8 stages -> result back in sA
}

// ---------------- kernel 1: forward FFT of A along y -------------------------
__global__ void k_fftA_y(const float* __restrict__ A) {
    __shared__ float2 sA[256];
    __shared__ float2 sB[256];
    int x = blockIdx.x;       // row
    int c = blockIdx.y;       // channel
    int t = threadIdx.x;      // 0..127
    sA[t]       = make_float2(A[(x * 256 + t) * 3 + c], 0.f);
    sA[t + 128] = make_float2(A[(x * 256 + t + 128) * 3 + c], 0.f);
    __syncthreads();
    fft256<-1>(sA, sB, t);
    g_fA[c * NPIX + x * 256 + t]       = sA[t];
    g_fA[c * NPIX + x * 256 + t + 128] = sA[t + 128];
}

// ---------------- kernel 2: forward FFT along x (in place) -------------------
__global__ void k_fftA_x() {
    __shared__ float2 sA[256];
    __shared__ float2 sB[256];
    int y = blockIdx.x;
    int c = blockIdx.y;
    int t = threadIdx.x;
    sA[t]       = g_fA[c * NPIX + t * 256 + y];
    sA[t + 128] = g_fA[c * NPIX + (t + 128) * 256 + y];
    __syncthreads();
    fft256<-1>(sA, sB, t);
    g_fA[c * NPIX + t * 256 + y]       = sA[t];
    g_fA[c * NPIX + (t + 128) * 256 + y] = sA[t + 128];
}

// ---------------- kernel 3: spectral multiply + inverse FFT along y ----------
__global__ void k_mult_ifft_y(const float* __restrict__ fKr,
                              const float* __restrict__ fKi) {
    __shared__ float2 sA[256];
    __shared__ float2 sB[256];
    int x = blockIdx.x;
    int k = blockIdx.y;
    int t = threadIdx.x;
    int c0 = k % 3;
#pragma unroll
    for (int j = 0; j < 2; j++) {
        int yy = t + j * 128;
        float2 fa = g_fA[c0 * NPIX + x * 256 + yy];
        int gi = (x * 256 + yy) * 15 + k;
        float2 fk = make_float2(fKr[gi], fKi[gi]);
        sA[yy] = cmulf(fk, fa);
    }
    __syncthreads();
    fft256<+1>(sA, sB, t);
    const float inv = 1.f / 256.f;
    g_spec[k * NPIX + x * 256 + t] =
        make_float2(sA[t].x * inv, sA[t].y * inv);
    g_spec[k * NPIX + x * 256 + t + 128] =
        make_float2(sA[t + 128].x * inv, sA[t + 128].y * inv);
}

// ---------------- kernel 4: inverse FFT along x + growth*P -------------------
__global__ void k_ifft_x_growth(const float* __restrict__ P,
                                const float* __restrict__ m,
                                const float* __restrict__ s) {
    __shared__ float2 sA[256];
    __shared__ float2 sB[256];
    int y = blockIdx.x;
    int k = blockIdx.y;
    int t = threadIdx.x;
    sA[t]       = g_spec[k * NPIX + t * 256 + y];
    sA[t + 128] = g_spec[k * NPIX + (t + 128) * 256 + y];
    __syncthreads();
    fft256<+1>(sA, sB, t);
    float mk = m[k];
    float sk = s[k];
    float inv2s2 = 1.f / (2.f * sk * sk);
#pragma unroll
    for (int j = 0; j < 2; j++) {
        int x = t + j * 128;
        float u = sA[x].x * (1.f / 256.f);
        float du = u - mk;
        float g = 2.f * expf(-du * du * inv2s2) - 1.f;
        g_Ug[k * NPIX + x * 256 + y] = g * P[(x * 256 + y) * 15 + k];
    }
}

// ---------------- kernel 5: channel reduction + Asum -------------------------
__global__ void k_chansum(const float* __restrict__ A) {
    int i = blockIdx.x * blockDim.x + threadIdx.x;
    if (i >= NPIX) return;
    float as = 0.f;
#pragma unroll
    for (int c = 0; c < 3; c++) {
        float u = 0.f;
#pragma unroll
        for (int j = 0; j < 5; j++) u += g_Ug[(c + 3 * j) * NPIX + i];
        g_Uc[c * NPIX + i] = u;
        as += A[i * 3 + c];
    }
    g_Asum[i] = as;
}

// zero-padded plane load
__device__ __forceinline__ float ldz(const float* __restrict__ p, int x, int y) {
    if ((unsigned)x > 255u || (unsigned)y > 255u) return 0.f;
    return p[x * 256 + y];
}

// ---------------- kernel 6: sobel + alpha mix + target centers ---------------
__global__ void k_flow(const float* __restrict__ A) {
    int i = blockIdx.x * blockDim.x + threadIdx.x;
    if (i >= NPIX) return;
    int x = i >> 8;
    int y = i & 255;
    const float MA = 4.35f;  // DD - SIGMA

    // Cg = sobel(Asum)
    float am1m1 = ldz(g_Asum, x - 1, y - 1), am10 = ldz(g_Asum, x - 1, y), am1p1 = ldz(g_Asum, x - 1, y + 1);
    float a0m1  = ldz(g_Asum, x,     y - 1),                              a0p1  = ldz(g_Asum, x,     y + 1);
    float ap1m1 = ldz(g_Asum, x + 1, y - 1), ap10 = ldz(g_Asum, x + 1, y), ap1p1 = ldz(g_Asum, x + 1, y + 1);
    float cg0 = (ap1m1 + 2.f * ap10 + ap1p1) - (am1m1 + 2.f * am10 + am1p1);
    float cg1 = (am1p1 + 2.f * a0p1 + ap1p1) - (am1m1 + 2.f * a0m1 + ap1m1);

    float px = (float)x + 0.5f;
    float py = (float)y + 0.5f;

#pragma unroll
    for (int c = 0; c < 3; c++) {
        const float* U = g_Uc + c * NPIX;
        float um1m1 = ldz(U, x - 1, y - 1), um10 = ldz(U, x - 1, y), um1p1 = ldz(U, x - 1, y + 1);
        float u0m1  = ldz(U, x,     y - 1),                          u0p1  = ldz(U, x,     y + 1);
        float up1m1 = ldz(U, x + 1, y - 1), up10 = ldz(U, x + 1, y), up1p1 = ldz(U, x + 1, y + 1);
        float f0 = (up1m1 + 2.f * up10 + up1p1) - (um1m1 + 2.f * um10 + um1p1);
        float f1 = (um1p1 + 2.f * u0p1 + up1p1) - (um1m1 + 2.f * u0m1 + up1m1);

        float a = A[i * 3 + c] * 0.5f;
        float alpha = fminf(a * a, 1.f);
        float oma = 1.f - alpha;
        f0 = fminf(fmaxf(f0 * oma - cg0 * alpha, -MA), MA);
        f1 = fminf(fmaxf(f1 * oma - cg1 * alpha, -MA), MA);

        float mu0 = fminf(fmaxf(px + 0.2f * f0, 0.65f), 255.35f);
        float mu1 = fminf(fmaxf(py + 0.2f * f1, 0.65f), 255.35f);
        g_mus[i * 6 + c * 2 + 0] = mu0;
        g_mus[i * 6 + c * 2 + 1] = mu1;
    }
}

// ---------------- kernel 7: reintegration gather (25 shifts, exact) ----------
__global__ void k_reint(const float* __restrict__ A,
                        const float* __restrict__ P,
                        float* __restrict__ out) {
    int i = blockIdx.x * blockDim.x + threadIdx.x;
    if (i >= NPIX) return;
    int x = i >> 8;
    int y = i & 255;
    float px = (float)x + 0.5f;
    float py = (float)y + 0.5f;
    const float invA = 1.f / 1.69f;  // 1/(4*sigma^2)

    float sumA0 = 0.f, sumA1 = 0.f, sumA2 = 0.f;
    float sP[15];
#pragma unroll
    for (int k = 0; k < 15; k++) sP[k] = 0.f;
    float wsum = 0.f;

#pragma unroll
    for (int dx = -2; dx <= 2; dx++) {
        int sx = (x - dx) & 255;
#pragma unroll
        for (int dy = -2; dy <= 2; dy++) {
            int sy = (y - dy) & 255;
            int b = sx * 256 + sy;
            float snA = 0.f;
#pragma unroll
            for (int c = 0; c < 3; c++) {
                float mu0 = g_mus[b * 6 + c * 2 + 0];
                float mu1 = g_mus[b * 6 + c * 2 + 1];
                float a0 = 1.15f - fabsf(px - mu0);   // 0.5 - d + sigma
                float a1 = 1.15f - fabsf(py - mu1);
                a0 = fminf(fmaxf(a0, 0.f), 1.f);
                a1 = fminf(fmaxf(a1, 0.f), 1.f);
                float area = a0 * a1 * invA;
                float v = A[b * 3 + c] * area;
                if (c == 0) sumA0 += v;
                else if (c == 1) sumA1 += v;
                else sumA2 += v;
                snA += v;
            }
            if (snA > 0.f) {
                float w = expf(snA) - 1.f;
                wsum += w;
#pragma unroll
                for (int k = 0; k < 15; k++) sP[k] += P[b * 15 + k] * w;
            }
        }
    }

    out[i * 3 + 0] = sumA0;
    out[i * 3 + 1] = sumA1;
    out[i * 3 + 2] = sumA2;
    float invw = 1.f / (wsum + 1e-10f);
    float* outP = out + 3 * NPIX;
#pragma unroll
    for (int k = 0; k < 15; k++) outP[i * 15 + k] = sP[k] * invw;
}

// ---------------- launcher ---------------------------------------------------
extern "C" void kernel_launch(void* const* d_in, const int* in_sizes, int n_in,
                              void* d_out, int out_size) {
    const float* A   = (const float*)d_in[0];
    const float* P   = (const float*)d_in[1];
    const float* fKr = (const float*)d_in[2];
    const float* fKi = (const float*)d_in[3];
    const float* m   = (const float*)d_in[4];
    const float* s   = (const float*)d_in[5];
    float* out = (float*)d_out;

    k_fftA_y<<<dim3(256, 3), 128>>>(A);
    k_fftA_x<<<dim3(256, 3), 128>>>();
    k_mult_ifft_y<<<dim3(256, 15), 128>>>(fKr, fKi);
    k_ifft_x_growth<<<dim3(256, 15), 128>>>(P, m, s);
    k_chansum<<<256, 256>>>(A);
    k_flow<<<256, 256>>>(A);
    k_reint<<<256, 256>>>(A, P, out);
}